// round 9
// baseline (speedup 1.0000x reference)
#include <cuda_runtime.h>

#define N_USR 50000
#define N_ENT 100000
#define DD 64
#define NE 1000000
#define NEI 500000

// ---- scratch (device globals; no allocation allowed) ----
__device__ __align__(16) float g_P[N_ENT * DD];       // src @ W_Q
__device__ __align__(16) float g_eL1[N_ENT * DD];     // entity emb after layer 1
__device__ __align__(16) float g_eL2[N_ENT * DD];     // entity emb after layer 2
__device__ __align__(16) float g_esum[N_ENT * DD];    // running sum of entity embs
// CSR (entities by head)
__device__ int      g_cnt[N_ENT];
__device__ int      g_rs[N_ENT + 1];
__device__ int      g_cur[N_ENT];
__device__ unsigned g_epk[NE];       // tail | (etype-1)<<17
// CSR (inter-edges by user)
__device__ int   g_ucnt[N_USR];
__device__ int   g_urs[N_USR + 1];
__device__ int   g_ucur[N_USR];
__device__ uint2 g_uedge[NEI];       // {item, bits(w)}

// ---- init: esum = entity_emb; d_out user region = user_emb; zero histograms ----
__global__ void k_init(const float4* __restrict__ ue, const float4* __restrict__ ee,
                       float4* __restrict__ uout) {
    int i = blockIdx.x * blockDim.x + threadIdx.x;
    if (i < N_ENT * DD / 4) ((float4*)g_esum)[i] = ee[i];
    if (i < N_USR * DD / 4) uout[i] = ue[i];
    if (i < N_ENT) g_cnt[i] = 0;
    if (i < N_USR) g_ucnt[i] = 0;
}

// ---- histograms: edge heads + inter-edge users ----
__global__ void k_hist(const int* __restrict__ head, const int* __restrict__ iu) {
    int e = blockIdx.x * blockDim.x + threadIdx.x;
    if (e < NE)  atomicAdd(&g_cnt[__ldg(&head[e])], 1);
    if (e < NEI) atomicAdd(&g_ucnt[__ldg(&iu[e])], 1);
}

// ---- exclusive scan, one block per array (block 0: entities, block 1: users) ----
__global__ void k_scan() {
    __shared__ int s[1024];
    const int n    = (blockIdx.x == 0) ? N_ENT : N_USR;
    const int* cnt = (blockIdx.x == 0) ? g_cnt : g_ucnt;
    int* rs        = (blockIdx.x == 0) ? g_rs : g_urs;
    int* cur       = (blockIdx.x == 0) ? g_cur : g_ucur;
    int tid = threadIdx.x;
    int chunk = (n + 1023) / 1024;
    int b = tid * chunk, e = min(b + chunk, n);
    int sum = 0;
    for (int i = b; i < e; i++) sum += cnt[i];
    s[tid] = sum;
    __syncthreads();
    for (int off = 1; off < 1024; off <<= 1) {
        int v = (tid >= off) ? s[tid - off] : 0;
        __syncthreads();
        s[tid] += v;
        __syncthreads();
    }
    int run = (tid == 0) ? 0 : s[tid - 1];
    for (int i = b; i < e; i++) {
        rs[i] = run;
        cur[i] = run;
        run += cnt[i];
    }
    if (tid == 1023) rs[n] = s[1023];
}

// ---- scatter edges into CSR order ----
__global__ void k_fill(const int* __restrict__ head, const int* __restrict__ tail,
                       const int* __restrict__ et,
                       const int* __restrict__ iu, const int* __restrict__ ii,
                       const float* __restrict__ w) {
    int e = blockIdx.x * blockDim.x + threadIdx.x;
    if (e < NE) {
        int pos = atomicAdd(&g_cur[__ldg(&head[e])], 1);
        g_epk[pos] = (unsigned)__ldg(&tail[e]) | ((unsigned)(__ldg(&et[e]) - 1) << 17);
    }
    if (e < NEI) {
        int pos = atomicAdd(&g_ucur[__ldg(&iu[e])], 1);
        g_uedge[pos] = make_uint2((unsigned)__ldg(&ii[e]), __float_as_uint(__ldg(&w[e])));
    }
}

// ---- P = src @ W_Q ; warp handles 4 rows, lane owns 2 output cols ----
__global__ void k_gemm(const float* __restrict__ ein, int layer,
                       const float* __restrict__ W) {
    const float* src = (layer == 0) ? ein : g_eL1;
    __shared__ float sW[DD * DD];
    for (int i = threadIdx.x; i < DD * DD; i += 256) sW[i] = W[i];
    __syncthreads();
    int warp = threadIdx.x >> 5, lane = threadIdx.x & 31;
    int r0 = (blockIdx.x * 8 + warp) * 4;
    if (r0 >= N_ENT) return;
    const float* e0 = &src[(size_t)r0 * DD];
    float acc[8] = {0.f, 0.f, 0.f, 0.f, 0.f, 0.f, 0.f, 0.f};
    #pragma unroll 4
    for (int k = 0; k < DD; k += 4) {
        float4 a[4];
        #pragma unroll
        for (int rr = 0; rr < 4; rr++) a[rr] = *(const float4*)&e0[rr * DD + k];
        #pragma unroll
        for (int j = 0; j < 4; j++) {
            float2 wv = *(const float2*)&sW[(k + j) * DD + lane * 2];
            #pragma unroll
            for (int rr = 0; rr < 4; rr++) {
                float av = (j == 0) ? a[rr].x : (j == 1) ? a[rr].y : (j == 2) ? a[rr].z : a[rr].w;
                acc[rr * 2]     += av * wv.x;
                acc[rr * 2 + 1] += av * wv.y;
            }
        }
    }
    #pragma unroll
    for (int rr = 0; rr < 4; rr++)
        *(float2*)&g_P[(size_t)(r0 + rr) * DD + lane * 2] =
            make_float2(acc[rr * 2], acc[rr * 2 + 1]);
}

// ---- fused per-entity aggregation (warp per row):
//      score -> exp -> weighted value sum -> /den -> L2 norm -> dst, esum +=
//      lanes 0-15 = head 0 (dims 0-31), 16-31 = head 1 ----
__global__ void k_agg(const float* __restrict__ ein, int layer,
                      const float* __restrict__ rel) {
    const float* src = (layer == 0) ? ein : g_eL1;
    float* dst       = (layer == 0) ? g_eL1 : g_eL2;
    __shared__ float s_rel[16 * DD];
    for (int i = threadIdx.x; i < 16 * DD; i += blockDim.x) s_rel[i] = rel[i];
    __syncthreads();
    int row = (blockIdx.x * blockDim.x + threadIdx.x) >> 5;
    int lane = threadIdx.x & 31;
    if (row >= N_ENT) return;
    int beg = g_rs[row], end = g_rs[row + 1];
    float2 q = *(const float2*)&g_P[(size_t)row * DD + lane * 2];
    float ax = 0.f, ay = 0.f, den = 0.f;
    const float inv = 0.17677669529663688f;  // 1/sqrt(32)
    for (int i = beg; i < end; i++) {
        unsigned pk = __ldg(&g_epk[i]);
        int t = pk & 0x1FFFF;
        float2 rl = *(const float2*)&s_rel[(pk >> 17) * DD + lane * 2];
        float2 pt = *(const float2*)&g_P[(size_t)t * DD + lane * 2];
        float p = q.x * pt.x * rl.x + q.y * pt.y * rl.y;
        p += __shfl_xor_sync(0xffffffffu, p, 1);
        p += __shfl_xor_sync(0xffffffffu, p, 2);
        p += __shfl_xor_sync(0xffffffffu, p, 4);
        p += __shfl_xor_sync(0xffffffffu, p, 8);
        float ex = __expf(p * inv);
        float2 v = *(const float2*)&src[(size_t)t * DD + lane * 2];
        ax += ex * v.x * rl.x;
        ay += ex * v.y * rl.y;
        den += ex;
    }
    float invd = (den > 0.f) ? (1.f / den) : 0.f;
    ax *= invd; ay *= invd;
    float ss = ax * ax + ay * ay;
    #pragma unroll
    for (int m = 1; m < 32; m <<= 1) ss += __shfl_xor_sync(0xffffffffu, ss, m);
    float nrm = 1.f / fmaxf(sqrtf(ss), 1e-12f);
    float ex0 = ax * nrm, ey0 = ay * nrm;
    *(float2*)&dst[(size_t)row * DD + lane * 2] = make_float2(ex0, ey0);
    float2* es = (float2*)&g_esum[(size_t)row * DD + lane * 2];
    float2 o = *es;
    *es = make_float2(o.x + ex0, o.y + ey0);
}

// ---- per-user aggregation (warp per user): uout += sum w * src[item] ----
__global__ void k_useragg(const float* __restrict__ ein, int layer,
                          float* __restrict__ uout) {
    const float* src = (layer == 0) ? ein : g_eL1;
    int u = (blockIdx.x * blockDim.x + threadIdx.x) >> 5;
    int lane = threadIdx.x & 31;
    if (u >= N_USR) return;
    int beg = g_urs[u], end = g_urs[u + 1];
    float ax = 0.f, ay = 0.f;
    for (int i = beg; i < end; i++) {
        uint2 e = __ldg(&g_uedge[i]);
        float ww = __uint_as_float(e.y);
        float2 v = *(const float2*)&src[(size_t)e.x * DD + lane * 2];
        ax += ww * v.x;
        ay += ww * v.y;
    }
    float2* o = (float2*)&uout[(size_t)u * DD + lane * 2];
    float2 c = *o;
    *o = make_float2(c.x + ax, c.y + ay);
}

// ---- final: scale user sums, write entity means ----
__global__ void k_final(float* __restrict__ out) {
    int i = blockIdx.x * blockDim.x + threadIdx.x;
    const float th = 1.f / 3.f;
    if (i < N_ENT * DD / 4) {
        float4 v = ((float4*)g_esum)[i];
        float4* oe = (float4*)(out + (size_t)N_USR * DD);
        oe[i] = make_float4(v.x * th, v.y * th, v.z * th, v.w * th);
    }
    if (i < N_USR * DD / 4) {
        float4* uo = (float4*)out;
        float4 v = uo[i];
        uo[i] = make_float4(v.x * th, v.y * th, v.z * th, v.w * th);
    }
}

extern "C" void kernel_launch(void* const* d_in, const int* in_sizes, int n_in,
                              void* d_out, int out_size) {
    // inputs: layers_num, user_emb, entity_emb, inter_edge, inter_edge_w,
    //         edge_index, edge_type, relation_emb, W_Q
    const float* user_emb = (const float*)d_in[1];
    const float* ent_emb  = (const float*)d_in[2];
    const int*   inter    = (const int*)d_in[3];
    const float* iw       = (const float*)d_in[4];
    const int*   eidx     = (const int*)d_in[5];
    const int*   etype    = (const int*)d_in[6];
    const float* rel      = (const float*)d_in[7];
    const float* WQ       = (const float*)d_in[8];
    const int* head = eidx;
    const int* tail = eidx + NE;
    const int* iu = inter;
    const int* ii = inter + NEI;
    float* out = (float*)d_out;

    const int T = 256;
    const int nE4 = N_ENT * DD / 4;  // 1.6M

    k_init<<<(nE4 + T - 1) / T, T>>>((const float4*)user_emb, (const float4*)ent_emb,
                                     (float4*)out);
    k_hist<<<(NE + T - 1) / T, T>>>(head, iu);
    k_scan<<<2, 1024>>>();
    k_fill<<<(NE + T - 1) / T, T>>>(head, tail, etype, iu, ii, iw);
    for (int l = 0; l < 2; l++) {
        k_gemm<<<N_ENT / 32, 256>>>(ent_emb, l, WQ);
        k_useragg<<<(N_USR * 32 + T - 1) / T, T>>>(ent_emb, l, out);
        k_agg<<<(N_ENT * 32 + T - 1) / T, T>>>(ent_emb, l, rel);
    }
    k_final<<<(nE4 + T - 1) / T, T>>>(out);
}

// round 11
// speedup vs baseline: 1.0121x; 1.0121x over previous
#include <cuda_runtime.h>

#define N_USR 50000
#define N_ENT 100000
#define DD 64
#define NE 1000000
#define NEI 500000

// ---- scratch (device globals; no allocation allowed) ----
__device__ __align__(16) float g_PV[N_ENT * 128];     // interleaved {P2l,P2l+1,v2l,v2l+1}
__device__ __align__(16) float g_eL1[N_ENT * DD];     // entity emb after layer 1
__device__ __align__(16) float g_esum[N_ENT * DD];    // running sum of entity embs
// CSR (entities by head)
__device__ int      g_cnt[N_ENT];
__device__ int      g_rs[N_ENT + 1];
__device__ int      g_cur[N_ENT];
__device__ unsigned g_epk[NE];       // tail | (etype-1)<<17
// CSR (inter-edges by user)
__device__ int   g_ucnt[N_USR];
__device__ int   g_urs[N_USR + 1];
__device__ int   g_ucur[N_USR];
__device__ uint2 g_uedge[NEI];       // {item, bits(w)}

// ---- init: esum = entity_emb; d_out user region = user_emb; zero histograms ----
__global__ void k_init(const float4* __restrict__ ue, const float4* __restrict__ ee,
                       float4* __restrict__ uout) {
    int i = blockIdx.x * blockDim.x + threadIdx.x;
    if (i < N_ENT * DD / 4) ((float4*)g_esum)[i] = ee[i];
    if (i < N_USR * DD / 4) uout[i] = ue[i];
    if (i < N_ENT) g_cnt[i] = 0;
    if (i < N_USR) g_ucnt[i] = 0;
}

// ---- histograms: edge heads + inter-edge users ----
__global__ void k_hist(const int* __restrict__ head, const int* __restrict__ iu) {
    int e = blockIdx.x * blockDim.x + threadIdx.x;
    if (e < NE)  atomicAdd(&g_cnt[__ldg(&head[e])], 1);
    if (e < NEI) atomicAdd(&g_ucnt[__ldg(&iu[e])], 1);
}

// ---- exclusive scan, one block per array (block 0: entities, block 1: users) ----
__global__ void k_scan() {
    __shared__ int s[1024];
    const int n    = (blockIdx.x == 0) ? N_ENT : N_USR;
    const int* cnt = (blockIdx.x == 0) ? g_cnt : g_ucnt;
    int* rs        = (blockIdx.x == 0) ? g_rs : g_urs;
    int* cur       = (blockIdx.x == 0) ? g_cur : g_ucur;
    int tid = threadIdx.x;
    int chunk = (n + 1023) / 1024;
    int b = tid * chunk, e = min(b + chunk, n);
    int sum = 0;
    for (int i = b; i < e; i++) sum += cnt[i];
    s[tid] = sum;
    __syncthreads();
    for (int off = 1; off < 1024; off <<= 1) {
        int v = (tid >= off) ? s[tid - off] : 0;
        __syncthreads();
        s[tid] += v;
        __syncthreads();
    }
    int run = (tid == 0) ? 0 : s[tid - 1];
    for (int i = b; i < e; i++) {
        rs[i] = run;
        cur[i] = run;
        run += cnt[i];
    }
    if (tid == 1023) rs[n] = s[1023];
}

// ---- scatter edges into CSR order ----
__global__ void k_fill(const int* __restrict__ head, const int* __restrict__ tail,
                       const int* __restrict__ et,
                       const int* __restrict__ iu, const int* __restrict__ ii,
                       const float* __restrict__ w) {
    int e = blockIdx.x * blockDim.x + threadIdx.x;
    if (e < NE) {
        int pos = atomicAdd(&g_cur[__ldg(&head[e])], 1);
        g_epk[pos] = (unsigned)__ldg(&tail[e]) | ((unsigned)(__ldg(&et[e]) - 1) << 17);
    }
    if (e < NEI) {
        int pos = atomicAdd(&g_ucur[__ldg(&iu[e])], 1);
        g_uedge[pos] = make_uint2((unsigned)__ldg(&ii[e]), __float_as_uint(__ldg(&w[e])));
    }
}

// ---- PV = {src @ W_Q, src} interleaved; warp handles 4 rows ----
__global__ void k_gemm(const float* __restrict__ ein, int layer,
                       const float* __restrict__ W) {
    const float* src = (layer == 0) ? ein : g_eL1;
    __shared__ float sW[DD * DD];
    for (int i = threadIdx.x; i < DD * DD; i += 256) sW[i] = W[i];
    __syncthreads();
    int warp = threadIdx.x >> 5, lane = threadIdx.x & 31;
    int r0 = (blockIdx.x * 8 + warp) * 4;
    if (r0 >= N_ENT) return;
    const float* e0 = &src[(size_t)r0 * DD];
    float acc[8] = {0.f, 0.f, 0.f, 0.f, 0.f, 0.f, 0.f, 0.f};
    #pragma unroll 4
    for (int k = 0; k < DD; k += 4) {
        float4 a[4];
        #pragma unroll
        for (int rr = 0; rr < 4; rr++) a[rr] = *(const float4*)&e0[rr * DD + k];
        #pragma unroll
        for (int j = 0; j < 4; j++) {
            float2 wv = *(const float2*)&sW[(k + j) * DD + lane * 2];
            #pragma unroll
            for (int rr = 0; rr < 4; rr++) {
                float av = (j == 0) ? a[rr].x : (j == 1) ? a[rr].y : (j == 2) ? a[rr].z : a[rr].w;
                acc[rr * 2]     += av * wv.x;
                acc[rr * 2 + 1] += av * wv.y;
            }
        }
    }
    #pragma unroll
    for (int rr = 0; rr < 4; rr++) {
        float2 v = *(const float2*)&e0[rr * DD + lane * 2];
        *(float4*)&g_PV[(size_t)(r0 + rr) * 128 + lane * 4] =
            make_float4(acc[rr * 2], acc[rr * 2 + 1], v.x, v.y);
    }
}

// ---- fused per-entity aggregation (warp per row, edge loop unrolled x4):
//      score -> exp -> weighted value sum -> /den -> L2 norm -> dst, esum +=
//      lanes 0-15 = head 0 (dims 0-31), 16-31 = head 1 ----
__global__ void k_agg(const float* __restrict__ ein, int layer,
                      const float* __restrict__ rel, float4* __restrict__ eout) {
    float* dst = (layer == 0) ? g_eL1 : (float*)eout;  // layer 1 writes mean directly
    __shared__ float s_rel[16 * DD];
    for (int i = threadIdx.x; i < 16 * DD; i += blockDim.x) s_rel[i] = rel[i];
    __syncthreads();
    int row = (blockIdx.x * blockDim.x + threadIdx.x) >> 5;
    int lane = threadIdx.x & 31;
    if (row >= N_ENT) return;
    int beg = g_rs[row], end = g_rs[row + 1];
    float4 qv = *(const float4*)&g_PV[(size_t)row * 128 + lane * 4];
    float qx = qv.x, qy = qv.y;
    float ax = 0.f, ay = 0.f, den = 0.f;
    const float inv = 0.17677669529663688f;  // 1/sqrt(32)
    int i = beg;
    for (; i + 4 <= end; i += 4) {
        unsigned pk[4];
        #pragma unroll
        for (int j = 0; j < 4; j++) pk[j] = __ldg(&g_epk[i + j]);
        float4 pv[4];
        #pragma unroll
        for (int j = 0; j < 4; j++)
            pv[j] = *(const float4*)&g_PV[(size_t)(pk[j] & 0x1FFFF) * 128 + lane * 4];
        float2 rl[4];
        #pragma unroll
        for (int j = 0; j < 4; j++)
            rl[j] = *(const float2*)&s_rel[(pk[j] >> 17) * DD + lane * 2];
        float pr[4];
        #pragma unroll
        for (int j = 0; j < 4; j++)
            pr[j] = qx * pv[j].x * rl[j].x + qy * pv[j].y * rl[j].y;
        #pragma unroll
        for (int m = 1; m <= 8; m <<= 1) {
            #pragma unroll
            for (int j = 0; j < 4; j++)
                pr[j] += __shfl_xor_sync(0xffffffffu, pr[j], m);
        }
        #pragma unroll
        for (int j = 0; j < 4; j++) {
            float ex = __expf(pr[j] * inv);
            ax += ex * pv[j].z * rl[j].x;
            ay += ex * pv[j].w * rl[j].y;
            den += ex;
        }
    }
    for (; i < end; i++) {
        unsigned pk = __ldg(&g_epk[i]);
        float4 pv = *(const float4*)&g_PV[(size_t)(pk & 0x1FFFF) * 128 + lane * 4];
        float2 rl = *(const float2*)&s_rel[(pk >> 17) * DD + lane * 2];
        float p = qx * pv.x * rl.x + qy * pv.y * rl.y;
        p += __shfl_xor_sync(0xffffffffu, p, 1);
        p += __shfl_xor_sync(0xffffffffu, p, 2);
        p += __shfl_xor_sync(0xffffffffu, p, 4);
        p += __shfl_xor_sync(0xffffffffu, p, 8);
        float ex = __expf(p * inv);
        ax += ex * pv.z * rl.x;
        ay += ex * pv.w * rl.y;
        den += ex;
    }
    float invd = (den > 0.f) ? (1.f / den) : 0.f;
    ax *= invd; ay *= invd;
    float ss = ax * ax + ay * ay;
    #pragma unroll
    for (int m = 1; m < 32; m <<= 1) ss += __shfl_xor_sync(0xffffffffu, ss, m);
    float nrm = 1.f / fmaxf(sqrtf(ss), 1e-12f);
    float ex0 = ax * nrm, ey0 = ay * nrm;
    float2* es = (float2*)&g_esum[(size_t)row * DD + lane * 2];
    float2 o = *es;
    if (layer == 0) {
        *(float2*)&dst[(size_t)row * DD + lane * 2] = make_float2(ex0, ey0);
        *es = make_float2(o.x + ex0, o.y + ey0);
    } else {
        // final entity output = (esum + e_layer2) / 3, written straight to d_out
        const float th = 1.f / 3.f;
        *(float2*)((float*)eout + (size_t)row * DD + lane * 2) =
            make_float2((o.x + ex0) * th, (o.y + ey0) * th);
    }
}

// ---- per-user aggregation (warp per user, unrolled x4) ----
__global__ void k_useragg(const float* __restrict__ ein, int layer,
                          float* __restrict__ uout) {
    const float* src = (layer == 0) ? ein : g_eL1;
    int u = (blockIdx.x * blockDim.x + threadIdx.x) >> 5;
    int lane = threadIdx.x & 31;
    if (u >= N_USR) return;
    int beg = g_urs[u], end = g_urs[u + 1];
    float ax = 0.f, ay = 0.f;
    int i = beg;
    for (; i + 4 <= end; i += 4) {
        uint2 e[4];
        #pragma unroll
        for (int j = 0; j < 4; j++) e[j] = __ldg(&g_uedge[i + j]);
        float2 v[4];
        #pragma unroll
        for (int j = 0; j < 4; j++)
            v[j] = *(const float2*)&src[(size_t)e[j].x * DD + lane * 2];
        #pragma unroll
        for (int j = 0; j < 4; j++) {
            float ww = __uint_as_float(e[j].y);
            ax += ww * v[j].x;
            ay += ww * v[j].y;
        }
    }
    for (; i < end; i++) {
        uint2 e = __ldg(&g_uedge[i]);
        float ww = __uint_as_float(e.y);
        float2 v = *(const float2*)&src[(size_t)e.x * DD + lane * 2];
        ax += ww * v.x;
        ay += ww * v.y;
    }
    float2* o = (float2*)&uout[(size_t)u * DD + lane * 2];
    float2 c = *o;
    if (layer == 0) {
        *o = make_float2(c.x + ax, c.y + ay);
    } else {
        const float th = 1.f / 3.f;
        *o = make_float2((c.x + ax) * th, (c.y + ay) * th);
    }
}

extern "C" void kernel_launch(void* const* d_in, const int* in_sizes, int n_in,
                              void* d_out, int out_size) {
    // inputs: layers_num, user_emb, entity_emb, inter_edge, inter_edge_w,
    //         edge_index, edge_type, relation_emb, W_Q
    const float* user_emb = (const float*)d_in[1];
    const float* ent_emb  = (const float*)d_in[2];
    const int*   inter    = (const int*)d_in[3];
    const float* iw       = (const float*)d_in[4];
    const int*   eidx     = (const int*)d_in[5];
    const int*   etype    = (const int*)d_in[6];
    const float* rel      = (const float*)d_in[7];
    const float* WQ       = (const float*)d_in[8];
    const int* head = eidx;
    const int* tail = eidx + NE;
    const int* iu = inter;
    const int* ii = inter + NEI;
    float* out = (float*)d_out;
    float* out_ent = out + (size_t)N_USR * DD;

    const int T = 256;
    const int nE4 = N_ENT * DD / 4;  // 1.6M

    k_init<<<(nE4 + T - 1) / T, T>>>((const float4*)user_emb, (const float4*)ent_emb,
                                     (float4*)out);
    k_hist<<<(NE + T - 1) / T, T>>>(head, iu);
    k_scan<<<2, 1024>>>();
    k_fill<<<(NE + T - 1) / T, T>>>(head, tail, etype, iu, ii, iw);
    for (int l = 0; l < 2; l++) {
        k_gemm<<<N_ENT / 32, 256>>>(ent_emb, l, WQ);
        k_useragg<<<(N_USR * 32 + T - 1) / T, T>>>(ent_emb, l, out);
        k_agg<<<(N_ENT * 32 + T - 1) / T, T>>>(ent_emb, l, rel, (float4*)out_ent);
    }
}